// round 7
// baseline (speedup 1.0000x reference)
#include <cuda_runtime.h>
#include <cuda_bf16.h>
#include <math.h>
#include <stdint.h>

#define HW 4096         // 64*64 spatial positions at feature res
#define CF 256          // feature channels
#define CO 64           // value channels (unalign_fb)
#define ALPHA 100.0f
#define NV 208          // GEMM2 cols: 3*64 warped + 3 E + 13 pad (13 n16 tiles)

// ---------------- device scratch (allocation-free) ----------------
__device__ uint32_t g_Xhi[(size_t)HW * HW / 2]; // bf16x2 hi plane (q,q+1)
__device__ uint32_t g_Xlo[(size_t)HW * HW / 2]; // bf16x2 lo plane
__device__ __nv_bfloat16 g_faHi[HW * CF];
__device__ __nv_bfloat16 g_faLo[HW * CF];
__device__ __nv_bfloat16 g_fbHi[HW * CF];
__device__ __nv_bfloat16 g_fbLo[HW * CF];
__device__ __nv_bfloat16 g_Vthi[NV * HW];    // V^T [col][q]
__device__ __nv_bfloat16 g_Vtlo[NV * HW];
__device__ float g_Wpart[4 * HW * NV];       // GEMM2 k-split partials
__device__ float g_ufb[HW * CO];             // downsampled values, [q][c]
__device__ float g_meanA[CF];
__device__ float g_meanB[CF];
__device__ unsigned char g_maskA[3 * HW];
__device__ unsigned char g_codeB[HW];        // 3-bit code of mask_b per q
__device__ float g_U0[CO];                   // sum_q ufb[q][c]
__device__ float g_Bk[3 * CO];               // B_k[c] = sum_{q in mb_k} ufb[q][c]
__device__ float g_nbk[3];                   // |mb_k|
__device__ float g_aligned[HW * CO];         // [p][c]

// ---------------- helpers ----------------
__device__ __forceinline__ uint32_t smem_u32(const void* p) {
    uint32_t a;
    asm("{ .reg .u64 t; cvta.to.shared.u64 t, %1; cvt.u32.u64 %0, t; }" : "=r"(a) : "l"(p));
    return a;
}

#define LDSM_X4(r0, r1, r2, r3, addr) \
    asm volatile("ldmatrix.sync.aligned.m8n8.x4.shared.b16 {%0,%1,%2,%3}, [%4];" \
        : "=r"(r0), "=r"(r1), "=r"(r2), "=r"(r3) : "r"(addr))

__device__ __forceinline__ void mma_bf16(float* c, const uint32_t* a, uint32_t b0, uint32_t b1) {
    asm volatile(
        "mma.sync.aligned.m16n8k16.row.col.f32.bf16.bf16.f32 "
        "{%0,%1,%2,%3}, {%4,%5,%6,%7}, {%8,%9}, {%0,%1,%2,%3};"
        : "+f"(c[0]), "+f"(c[1]), "+f"(c[2]), "+f"(c[3])
        : "r"(a[0]), "r"(a[1]), "r"(a[2]), "r"(a[3]), "r"(b0), "r"(b1));
}

__device__ __forceinline__ void cp16(uint32_t saddr, const void* g) {
    asm volatile("cp.async.cg.shared.global [%0], [%1], 16;" :: "r"(saddr), "l"(g));
}
#define CP_COMMIT asm volatile("cp.async.commit_group;" ::: "memory")
#define CP_WAIT1  asm volatile("cp.async.wait_group 1;" ::: "memory")
#define CP_WAIT0  asm volatile("cp.async.wait_group 0;" ::: "memory")

// ---------------- 1) masks ----------------
__global__ void k_masks(const int* __restrict__ fap, const int* __restrict__ fbp) {
    int p = blockIdx.x * 256 + threadIdx.x;
    if (p >= HW) return;
    int y = (p >> 6) << 2, x = (p & 63) << 2;
    int off = y * 256 + x;
    unsigned code = 0;
#pragma unroll
    for (int k = 0; k < 3; k++) {
        g_maskA[k * HW + p] = (fap[(k + 1) * 65536 + off] != 0) ? 1 : 0;
        if (fbp[(k + 1) * 65536 + off] != 0) code |= (1u << k);
    }
    g_codeB[p] = (unsigned char)code;
}

// ---------------- 2) per-channel spatial means ----------------
__global__ void k_mean(const float* __restrict__ fa, const float* __restrict__ fb) {
    int cb = blockIdx.x;
    int ch = cb & 255;
    const float* src = (cb < 256) ? fa : fb;
    float s = 0.f;
    for (int i = threadIdx.x; i < HW; i += 256) s += src[ch * HW + i];
    __shared__ float red[256];
    red[threadIdx.x] = s;
    __syncthreads();
    for (int st = 128; st > 0; st >>= 1) {
        if (threadIdx.x < st) red[threadIdx.x] += red[threadIdx.x + st];
        __syncthreads();
    }
    if (threadIdx.x == 0) {
        float m = red[0] / (float)HW;
        if (cb < 256) g_meanA[ch] = m; else g_meanB[ch] = m;
    }
}

// ---------------- 3) center + normalize + bf16 hi/lo split ----------------
__global__ void k_norm(const float* __restrict__ fa, const float* __restrict__ fb) {
    int p = blockIdx.x * 256 + threadIdx.x;
    if (p >= HW) return;
    const float* src;  const float* mean;
    __nv_bfloat16 *dHi, *dLo;
    if (blockIdx.y == 0) { src = fa; mean = g_meanA; dHi = g_faHi; dLo = g_faLo; }
    else                 { src = fb; mean = g_meanB; dHi = g_fbHi; dLo = g_fbLo; }
    float nsq = 0.f;
    for (int c = 0; c < CF; c++) {
        float v = src[c * HW + p] - mean[c];
        nsq += v * v;
    }
    float inv = rsqrtf(nsq);
    for (int c = 0; c < CF; c++) {
        float v = (src[c * HW + p] - mean[c]) * inv;
        __nv_bfloat16 h = __float2bfloat16(v);
        dHi[p * CF + c] = h;
        dLo[p * CF + c] = __float2bfloat16(v - __bfloat162float(h));
    }
}

// ---------------- 4) bilinear downsample 256->64 ----------------
__global__ void k_ufb(const float* __restrict__ ub) {
    int idx = blockIdx.x * 256 + threadIdx.x;
    if (idx >= HW * CO) return;
    int c = idx & 63, q = idx >> 6;
    int i = q >> 6, j = q & 63;
    const float sc = 255.0f / 63.0f;
    float ry = (float)i * sc, rx = (float)j * sc;
    int y0 = (int)ry, x0 = (int)rx;
    int y1 = min(y0 + 1, 255), x1 = min(x0 + 1, 255);
    float wy = ry - (float)y0, wx = rx - (float)x0;
    const float* b = ub + c * 65536;
    float v00 = b[y0 * 256 + x0], v01 = b[y0 * 256 + x1];
    float v10 = b[y1 * 256 + x0], v11 = b[y1 * 256 + x1];
    float r0 = v00 * (1.f - wy) + v10 * wy;
    float r1 = v01 * (1.f - wy) + v11 * wy;
    g_ufb[q * CO + c] = r0 * (1.f - wx) + r1 * wx;
}

// ---------------- 5) U0[c], Bk[k][c], nbk ----------------
__global__ void k_ub() {
    int c = blockIdx.x;
    __shared__ float s_acc[4];
    __shared__ int   s_n[3];
    if (threadIdx.x < 4) s_acc[threadIdx.x] = 0.f;
    if (threadIdx.x < 3) s_n[threadIdx.x] = 0;
    __syncthreads();
    float a0 = 0, b0 = 0, b1 = 0, b2 = 0;
    int n0 = 0, n1 = 0, n2 = 0;
    for (int q = threadIdx.x; q < HW; q += 256) {
        float u = g_ufb[q * CO + c];
        int code = g_codeB[q];
        a0 += u;
        if (code & 1) { b0 += u; n0++; }
        if (code & 2) { b1 += u; n1++; }
        if (code & 4) { b2 += u; n2++; }
    }
    atomicAdd(&s_acc[0], a0);
    atomicAdd(&s_acc[1], b0);
    atomicAdd(&s_acc[2], b1);
    atomicAdd(&s_acc[3], b2);
    if (c == 0) {
        atomicAdd(&s_n[0], n0); atomicAdd(&s_n[1], n1); atomicAdd(&s_n[2], n2);
    }
    __syncthreads();
    if (threadIdx.x == 0) g_U0[c] = s_acc[0];
    if (threadIdx.x < 3) {
        g_Bk[threadIdx.x * CO + c] = s_acc[1 + threadIdx.x];
        if (c == 0) g_nbk[threadIdx.x] = (float)s_n[threadIdx.x];
    }
}

// ---------------- 5b) build V^T planes ----------------
__global__ void k_V() {
    int idx = blockIdx.x * 256 + threadIdx.x;   // col*HW + q
    if (idx >= NV * HW) return;
    int col = idx >> 12, q = idx & 4095;
    float v = 0.f;
    int code = g_codeB[q];
    if (col < 192) {
        int k = col >> 6, c = col & 63;
        v = ((code >> k) & 1) ? g_ufb[q * CO + c] : 0.f;
    } else if (col < 195) {
        v = (float)((code >> (col - 192)) & 1);
    }
    __nv_bfloat16 h = __float2bfloat16(v);
    g_Vthi[idx] = h;
    g_Vtlo[idx] = __float2bfloat16(v - __bfloat162float(h));
}

// ---------------- 6) GEMM1: split-bf16 S-GEMM, 128x64 tile, 3 CTAs/SM ----------------
#define G1_APLANE 10240             // 128 rows * 80 bytes
#define G1_BPLANE 5120              // 64 rows * 80 bytes
#define G1_BUF   (2 * G1_APLANE + 2 * G1_BPLANE)  // 30720
#define G1_SMEM  (2 * G1_BUF)                     // 61440

__device__ __forceinline__ void g1_prefetch(uint32_t sb, int buf, int kc,
                                            int pb, int qb, int t) {
    int kof = kc * 32;
#pragma unroll
    for (int i = 0; i < 6; i++) {
        int v = t + i * 256;
        if (v < 1024) {   // A planes: 2 x 128 rows x 4 segs
            int plane = v >> 9, r = (v >> 2) & 127, seg = v & 3;
            uint32_t sa = sb + (uint32_t)(buf * G1_BUF + plane * G1_APLANE + r * 80 + seg * 16);
            const __nv_bfloat16* src = plane ? g_faLo : g_faHi;
            cp16(sa, (const char*)src + ((size_t)(pb + r) * CF + kof + seg * 8) * 2);
        } else {          // B planes: 2 x 64 rows x 4 segs
            int v2 = v - 1024;
            int plane = v2 >> 8, r = (v2 >> 2) & 63, seg = v2 & 3;
            uint32_t sa = sb + (uint32_t)(buf * G1_BUF + 2 * G1_APLANE + plane * G1_BPLANE + r * 80 + seg * 16);
            const __nv_bfloat16* src = plane ? g_fbLo : g_fbHi;
            cp16(sa, (const char*)src + ((size_t)(qb + r) * CF + kof + seg * 8) * 2);
        }
    }
}

__global__ void __launch_bounds__(256, 3) k_gemm_mma() {
    extern __shared__ char smem[];
    uint32_t sb = smem_u32(smem);
    int t = threadIdx.x, w = t >> 5, l = t & 31;
    int qb = blockIdx.x << 6, pb = blockIdx.y << 7;
    int wm = w & 3, wn = w >> 2;     // SMSP-balanced

    float acc[2][4][4] = {};

    int rowA = wm * 32 + (l & 15);
    int rowB = wn * 32 + (l & 15);
    uint32_t colb = (uint32_t)((l >> 4) << 4);

    g1_prefetch(sb, 0, 0, pb, qb, t); CP_COMMIT;

    for (int kc = 0; kc < 8; kc++) {
        if (kc < 7) { g1_prefetch(sb, (kc + 1) & 1, kc + 1, pb, qb, t); CP_COMMIT; CP_WAIT1; }
        else CP_WAIT0;
        __syncthreads();

        uint32_t baseA = sb + (uint32_t)((kc & 1) * G1_BUF);
        uint32_t baseB = baseA + 2 * G1_APLANE;

#pragma unroll
        for (int kk2 = 0; kk2 < 2; kk2++) {
            uint32_t kb = (uint32_t)(kk2 * 32) + colb;
            uint32_t ah[2][4], al[2][4], bh[2][4], bl[2][4];
#pragma unroll
            for (int mi = 0; mi < 2; mi++) {
                uint32_t ad = baseA + (uint32_t)((rowA + mi * 16) * 80) + kb;
                LDSM_X4(ah[mi][0], ah[mi][1], ah[mi][2], ah[mi][3], ad);
                LDSM_X4(al[mi][0], al[mi][1], al[mi][2], al[mi][3], ad + G1_APLANE);
            }
#pragma unroll
            for (int np = 0; np < 2; np++) {
                uint32_t bd = baseB + (uint32_t)((rowB + np * 16) * 80) + kb;
                LDSM_X4(bh[np][0], bh[np][1], bh[np][2], bh[np][3], bd);
                LDSM_X4(bl[np][0], bl[np][1], bl[np][2], bl[np][3], bd + G1_BPLANE);
            }
#pragma unroll
            for (int mi = 0; mi < 2; mi++)
#pragma unroll
                for (int np = 0; np < 2; np++) {
                    mma_bf16(acc[mi][np * 2 + 0], ah[mi], bh[np][0], bh[np][2]);
                    mma_bf16(acc[mi][np * 2 + 1], ah[mi], bh[np][1], bh[np][3]);
                    mma_bf16(acc[mi][np * 2 + 0], ah[mi], bl[np][0], bl[np][2]);
                    mma_bf16(acc[mi][np * 2 + 1], ah[mi], bl[np][1], bl[np][3]);
                    mma_bf16(acc[mi][np * 2 + 0], al[mi], bh[np][0], bh[np][2]);
                    mma_bf16(acc[mi][np * 2 + 1], al[mi], bh[np][1], bh[np][3]);
                }
        }
        __syncthreads();
    }

    // ---- epilogue: exp + bf16 hi/lo plane stores ----
    int prl = wm * 32 + (l >> 2);
    int qcl = wn * 32 + (l & 3) * 2;
#pragma unroll
    for (int mi = 0; mi < 2; mi++) {
#pragma unroll
        for (int nj = 0; nj < 4; nj++) {
#pragma unroll
            for (int half = 0; half < 2; half++) {
                int rloc = prl + mi * 16 + half * 8;
                int qloc = qcl + nj * 8;
                float x0 = __expf(fminf(ALPHA * acc[mi][nj][half * 2 + 0], 80.f));
                float x1 = __expf(fminf(ALPHA * acc[mi][nj][half * 2 + 1], 80.f));
                __nv_bfloat16 h0 = __float2bfloat16(x0);
                __nv_bfloat16 h1 = __float2bfloat16(x1);
                __nv_bfloat16 lo0 = __float2bfloat16(x0 - __bfloat162float(h0));
                __nv_bfloat16 lo1 = __float2bfloat16(x1 - __bfloat162float(h1));
                __nv_bfloat162 hp; hp.x = h0; hp.y = h1;
                __nv_bfloat162 lp; lp.x = lo0; lp.y = lo1;
                size_t idx = ((size_t)(pb + rloc) * HW + qb + qloc) >> 1;
                g_Xhi[idx] = *(uint32_t*)&hp;
                g_Xlo[idx] = *(uint32_t*)&lp;
            }
        }
    }
}

// ---------------- 7) GEMM2: W = X @ V^T, cp.async double-buffered ----------------
#define G2_APLANE (64 * 80)                      // 5120
#define G2_BPLANE (NV * 80)                      // 16640
#define G2_BUF    (2 * G2_APLANE + 2 * G2_BPLANE)// 43520
#define G2_SMEM   (2 * G2_BUF)                   // 87040
#define G2_SLOTS  (512 + 2 * NV * 4)             // 2176

__device__ __forceinline__ void g2_prefetch(uint32_t sb, int buf, int qof, int pb, int t) {
#pragma unroll
    for (int i = 0; i < 9; i++) {
        int v = t + i * 256;
        if (v >= G2_SLOTS) break;
        if (v < 512) {
            int plane = v >> 8, r = (v >> 2) & 63, seg = v & 3;
            uint32_t sa = sb + (uint32_t)(buf * G2_BUF + plane * G2_APLANE + r * 80 + seg * 16);
            const uint32_t* xp = plane ? g_Xlo : g_Xhi;
            cp16(sa, (const char*)xp + ((size_t)(pb + r) * HW + qof) * 2 + seg * 16);
        } else {
            int v2 = v - 512;
            int plane = (v2 >= NV * 4) ? 1 : 0;
            int r = (v2 - plane * NV * 4) >> 2, seg = v2 & 3;
            uint32_t sa = sb + (uint32_t)(buf * G2_BUF + 2 * G2_APLANE + plane * G2_BPLANE + r * 80 + seg * 16);
            const __nv_bfloat16* vp = plane ? g_Vtlo : g_Vthi;
            cp16(sa, (const char*)vp + ((size_t)r * HW + qof + seg * 8) * 2);
        }
    }
}

__global__ void __launch_bounds__(256, 2) k_gemm2() {
    extern __shared__ char smem[];
    uint32_t sb = smem_u32(smem);
    int t = threadIdx.x, w = t >> 5, l = t & 31;
    int pb = blockIdx.x << 6;
    int q0 = blockIdx.y << 10;
    int wm = w & 3, wn = w >> 2;     // SMSP-balanced; wn0: 7 tiles, wn1: 6 tiles
    int nt = wn ? 6 : 7;

    float acc[14][4] = {};

    uint32_t arow = (uint32_t)((wm * 16 + (l & 15)) * 80);
    uint32_t lofs = (uint32_t)((l >> 4) << 4);

    g2_prefetch(sb, 0, q0, pb, t); CP_COMMIT;

    for (int ch = 0; ch < 32; ch++) {
        if (ch < 31) { g2_prefetch(sb, (ch + 1) & 1, q0 + (ch + 1) * 32, pb, t); CP_COMMIT; CP_WAIT1; }
        else CP_WAIT0;
        __syncthreads();

        uint32_t baseA = sb + (uint32_t)((ch & 1) * G2_BUF);
        uint32_t baseB = baseA + 2 * G2_APLANE;

#pragma unroll
        for (int kk2 = 0; kk2 < 2; kk2++) {
            uint32_t kb = (uint32_t)(kk2 * 32) + lofs;
            uint32_t ah[4], al[4];
            uint32_t ad = baseA + arow + kb;
            LDSM_X4(ah[0], ah[1], ah[2], ah[3], ad);
            LDSM_X4(al[0], al[1], al[2], al[3], ad + G2_APLANE);
#pragma unroll
            for (int np = 0; np < 7; np++) {
                if (np < nt) {
                    uint32_t bd = baseB + (uint32_t)((wn * 112 + np * 16 + (l & 15)) * 80) + kb;
                    uint32_t bh[4], bl[4];
                    LDSM_X4(bh[0], bh[1], bh[2], bh[3], bd);
                    LDSM_X4(bl[0], bl[1], bl[2], bl[3], bd + G2_BPLANE);
                    mma_bf16(acc[np * 2 + 0], ah, bh[0], bh[2]);
                    mma_bf16(acc[np * 2 + 1], ah, bh[1], bh[3]);
                    mma_bf16(acc[np * 2 + 0], ah, bl[0], bl[2]);
                    mma_bf16(acc[np * 2 + 1], ah, bl[1], bl[3]);
                    mma_bf16(acc[np * 2 + 0], al, bh[0], bh[2]);
                    mma_bf16(acc[np * 2 + 1], al, bh[1], bh[3]);
                }
            }
        }
        __syncthreads();
    }

    // epilogue: fp32 partials
    int r0 = pb + wm * 16 + (l >> 2);
    int cb2 = (l & 3) * 2;
    float* Wp = g_Wpart + (size_t)blockIdx.y * HW * NV;
#pragma unroll
    for (int np = 0; np < 7; np++) {
        if (np < nt) {
#pragma unroll
            for (int n8 = 0; n8 < 2; n8++) {
                int col = wn * 112 + np * 16 + n8 * 8 + cb2;
                float* a = acc[np * 2 + n8];
                *(float2*)&Wp[(size_t)r0 * NV + col]       = make_float2(a[0], a[1]);
                *(float2*)&Wp[(size_t)(r0 + 8) * NV + col] = make_float2(a[2], a[3]);
            }
        }
    }
}

// ---------------- 8) combine (reads k-split partials directly) ----------------
__global__ void k_combine() {
    int idx = blockIdx.x * 256 + threadIdx.x;   // p*64 + c
    if (idx >= HW * CO) return;
    int p = idx >> 6, c = idx & 63;
    float comb = 0.f, msum = 0.f;
#pragma unroll
    for (int k = 0; k < 3; k++) {
        if (g_maskA[k * HW + p]) {
            msum += 1.f;
            float E = 0.f, Wv = 0.f;
#pragma unroll
            for (int ks = 0; ks < 4; ks++) {
                const float* Wp = g_Wpart + (size_t)ks * HW * NV + (size_t)p * NV;
                E  += Wp[192 + k];
                Wv += Wp[k * 64 + c];
            }
            float denom = E + (4096.0f - g_nbk[k]);
            comb += (Wv + g_U0[c] - g_Bk[k * CO + c]) / denom;
        }
    }
    g_aligned[idx] = comb / fmaxf(msum, 1.0f);
}

// ---------------- 9) bilinear upsample 64 -> 256 ----------------
__global__ void k_up(float* __restrict__ out) {
    int idx = blockIdx.x * 256 + threadIdx.x;
    if (idx >= CO * 65536) return;
    int c = idx >> 16, Y = (idx >> 8) & 255, X = idx & 255;
    const float sc = 63.0f / 255.0f;
    float ry = (float)Y * sc, rx = (float)X * sc;
    int y0 = (int)ry, x0 = (int)rx;
    int y1 = min(y0 + 1, 63), x1 = min(x0 + 1, 63);
    float wy = ry - (float)y0, wx = rx - (float)x0;
    const float* A = g_aligned;
    float v00 = A[((y0 << 6) + x0) * CO + c];
    float v01 = A[((y0 << 6) + x1) * CO + c];
    float v10 = A[((y1 << 6) + x0) * CO + c];
    float v11 = A[((y1 << 6) + x1) * CO + c];
    float r0 = v00 * (1.f - wy) + v10 * wy;
    float r1 = v01 * (1.f - wy) + v11 * wy;
    out[idx] = r0 * (1.f - wx) + r1 * wx;
}

// ---------------- launch ----------------
extern "C" void kernel_launch(void* const* d_in, const int* in_sizes, int n_in,
                              void* d_out, int out_size) {
    const float* ufb_in = (const float*)d_in[0];   // (1,64,256,256)
    const float* fa     = (const float*)d_in[1];   // (1,256,64,64)
    const int*   fap    = (const int*)  d_in[2];   // (1,4,256,256)
    const float* fb     = (const float*)d_in[3];   // (1,256,64,64)
    const int*   fbp    = (const int*)  d_in[4];   // (1,4,256,256)
    float* out = (float*)d_out;                    // (1,64,256,256)

    cudaFuncSetAttribute(k_gemm_mma, cudaFuncAttributeMaxDynamicSharedMemorySize, G1_SMEM);
    cudaFuncSetAttribute(k_gemm2,    cudaFuncAttributeMaxDynamicSharedMemorySize, G2_SMEM);

    k_masks<<<16, 256>>>(fap, fbp);
    k_mean<<<512, 256>>>(fa, fb);
    k_norm<<<dim3(16, 2), 256>>>(fa, fb);
    k_gemm_mma<<<dim3(64, 32), 256, G1_SMEM>>>();          // 4th launch -> profiled
    k_ufb<<<(HW * CO) / 256, 256>>>(ufb_in);
    k_ub<<<64, 256>>>();
    k_V<<<(NV * HW) / 256, 256>>>();
    k_gemm2<<<dim3(64, 4), 256, G2_SMEM>>>();
    k_combine<<<(HW * CO) / 256, 256>>>();
    k_up<<<(CO * 65536) / 256, 256>>>(out);
}

// round 8
// speedup vs baseline: 1.3974x; 1.3974x over previous
#include <cuda_runtime.h>
#include <cuda_bf16.h>
#include <math.h>
#include <stdint.h>

#define HW 4096         // 64*64 spatial positions at feature res
#define CF 256          // feature channels
#define CO 64           // value channels (unalign_fb)
#define ALPHA 100.0f
#define NV 208          // GEMM2 cols: 3*64 warped + 3 E + 13 pad (13 n16 tiles)

// ---------------- device scratch (allocation-free) ----------------
__device__ uint32_t g_Xhi[(size_t)HW * HW / 2]; // bf16x2 hi plane (q,q+1)
__device__ uint32_t g_Xlo[(size_t)HW * HW / 2]; // bf16x2 lo plane
__device__ __nv_bfloat16 g_faHi[HW * CF];
__device__ __nv_bfloat16 g_faLo[HW * CF];
__device__ __nv_bfloat16 g_fbHi[HW * CF];
__device__ __nv_bfloat16 g_fbLo[HW * CF];
__device__ __nv_bfloat16 g_Vthi[NV * HW];    // V^T [col][q]
__device__ __nv_bfloat16 g_Vtlo[NV * HW];
__device__ float g_Wpart[4 * HW * NV];       // GEMM2 k-split partials
__device__ float g_ufb[HW * CO];             // downsampled values, [q][c]
__device__ float g_meanA[CF];
__device__ float g_meanB[CF];
__device__ unsigned char g_maskA[3 * HW];
__device__ unsigned char g_codeB[HW];        // 3-bit code of mask_b per q
__device__ float g_U0[CO];                   // sum_q ufb[q][c]
__device__ float g_Bk[3 * CO];               // B_k[c] = sum_{q in mb_k} ufb[q][c]
__device__ float g_nbk[3];                   // |mb_k|
__device__ float g_aligned[HW * CO];         // [p][c]

// ---------------- helpers ----------------
__device__ __forceinline__ uint32_t smem_u32(const void* p) {
    uint32_t a;
    asm("{ .reg .u64 t; cvta.to.shared.u64 t, %1; cvt.u32.u64 %0, t; }" : "=r"(a) : "l"(p));
    return a;
}

#define LDSM_X4(r0, r1, r2, r3, addr) \
    asm volatile("ldmatrix.sync.aligned.m8n8.x4.shared.b16 {%0,%1,%2,%3}, [%4];" \
        : "=r"(r0), "=r"(r1), "=r"(r2), "=r"(r3) : "r"(addr))

__device__ __forceinline__ void mma_bf16(float* c, const uint32_t* a, uint32_t b0, uint32_t b1) {
    asm volatile(
        "mma.sync.aligned.m16n8k16.row.col.f32.bf16.bf16.f32 "
        "{%0,%1,%2,%3}, {%4,%5,%6,%7}, {%8,%9}, {%0,%1,%2,%3};"
        : "+f"(c[0]), "+f"(c[1]), "+f"(c[2]), "+f"(c[3])
        : "r"(a[0]), "r"(a[1]), "r"(a[2]), "r"(a[3]), "r"(b0), "r"(b1));
}

__device__ __forceinline__ void cp16(uint32_t saddr, const void* g) {
    asm volatile("cp.async.cg.shared.global [%0], [%1], 16;" :: "r"(saddr), "l"(g));
}
#define CP_COMMIT asm volatile("cp.async.commit_group;" ::: "memory")
#define CP_WAIT2  asm volatile("cp.async.wait_group 2;" ::: "memory")

// ---------------- 1) masks ----------------
__global__ void k_masks(const int* __restrict__ fap, const int* __restrict__ fbp) {
    int p = blockIdx.x * 256 + threadIdx.x;
    if (p >= HW) return;
    int y = (p >> 6) << 2, x = (p & 63) << 2;
    int off = y * 256 + x;
    unsigned code = 0;
#pragma unroll
    for (int k = 0; k < 3; k++) {
        g_maskA[k * HW + p] = (fap[(k + 1) * 65536 + off] != 0) ? 1 : 0;
        if (fbp[(k + 1) * 65536 + off] != 0) code |= (1u << k);
    }
    g_codeB[p] = (unsigned char)code;
}

// ---------------- 2) per-channel spatial means ----------------
__global__ void k_mean(const float* __restrict__ fa, const float* __restrict__ fb) {
    int cb = blockIdx.x;
    int ch = cb & 255;
    const float* src = (cb < 256) ? fa : fb;
    float s = 0.f;
    for (int i = threadIdx.x; i < HW; i += 256) s += src[ch * HW + i];
    __shared__ float red[256];
    red[threadIdx.x] = s;
    __syncthreads();
    for (int st = 128; st > 0; st >>= 1) {
        if (threadIdx.x < st) red[threadIdx.x] += red[threadIdx.x + st];
        __syncthreads();
    }
    if (threadIdx.x == 0) {
        float m = red[0] / (float)HW;
        if (cb < 256) g_meanA[ch] = m; else g_meanB[ch] = m;
    }
}

// ---------------- 3) center + normalize + split, smem-transposed (coalesced) ----------------
// block: 32 p x 256 c, 256 threads. grid (128, 2).
__global__ void __launch_bounds__(256) k_norm(const float* __restrict__ fa,
                                              const float* __restrict__ fb) {
    __shared__ float sm[256 * 33];     // [c][p], stride 33 words
    int t = threadIdx.x;
    int pb = blockIdx.x * 32;
    const float* src;  const float* mean;
    __nv_bfloat16 *dHi, *dLo;
    if (blockIdx.y == 0) { src = fa; mean = g_meanA; dHi = g_faHi; dLo = g_faLo; }
    else                 { src = fb; mean = g_meanB; dHi = g_fbHi; dLo = g_fbLo; }

    // load + center: coalesced 32-wide in p
#pragma unroll
    for (int i = 0; i < 32; i++) {
        int v = t + i * 256;           // v < 8192
        int c = v >> 5, p = v & 31;
        sm[c * 33 + p] = src[c * HW + pb + p] - mean[c];
    }
    __syncthreads();

    int p = t >> 3, part = t & 7;      // 8 threads per p, each owns 32 c
    float nsq = 0.f;
#pragma unroll
    for (int j = 0; j < 32; j++) {
        int c = part * 32 + ((j + part * 4) & 31);
        float v = sm[c * 33 + p];
        nsq += v * v;
    }
    nsq += __shfl_xor_sync(0xFFFFFFFF, nsq, 1);
    nsq += __shfl_xor_sync(0xFFFFFFFF, nsq, 2);
    nsq += __shfl_xor_sync(0xFFFFFFFF, nsq, 4);
    float inv = rsqrtf(nsq);

    // store: thread t writes 64 contiguous bytes at byte offset t*64 within block row range
    uint4 outH[2], outL[2];
#pragma unroll
    for (int g = 0; g < 2; g++) {
        uint32_t* oh = (uint32_t*)&outH[g];
        uint32_t* ol = (uint32_t*)&outL[g];
#pragma unroll
        for (int j = 0; j < 4; j++) {
            int c = part * 32 + g * 16 + j * 4;
            float v0 = sm[(c + 0) * 33 + p] * inv;
            float v1 = sm[(c + 1) * 33 + p] * inv;
            float v2 = sm[(c + 2) * 33 + p] * inv;
            float v3 = sm[(c + 3) * 33 + p] * inv;
            // pack pairs: process (v0,v1) into word j? need 2 words per 4 c
            __nv_bfloat16 h0 = __float2bfloat16(v0), h1 = __float2bfloat16(v1);
            __nv_bfloat16 h2 = __float2bfloat16(v2), h3 = __float2bfloat16(v3);
            __nv_bfloat162 hp01; hp01.x = h0; hp01.y = h1;
            __nv_bfloat162 hp23; hp23.x = h2; hp23.y = h3;
            __nv_bfloat16 l0 = __float2bfloat16(v0 - __bfloat162float(h0));
            __nv_bfloat16 l1 = __float2bfloat16(v1 - __bfloat162float(h1));
            __nv_bfloat16 l2 = __float2bfloat16(v2 - __bfloat162float(h2));
            __nv_bfloat16 l3 = __float2bfloat16(v3 - __bfloat162float(h3));
            __nv_bfloat162 lp01; lp01.x = l0; lp01.y = l1;
            __nv_bfloat162 lp23; lp23.x = l2; lp23.y = l3;
            if (j < 2) {
                oh[j * 2 + 0] = *(uint32_t*)&hp01; oh[j * 2 + 1] = *(uint32_t*)&hp23;
                ol[j * 2 + 0] = *(uint32_t*)&lp01; ol[j * 2 + 1] = *(uint32_t*)&lp23;
            } else {
                oh[(j - 2) * 2 + 0] = 0; // placeholder, overwritten below
            }
            // simpler: write directly per 4-c group
            if (j >= 2) { }
        }
        (void)oh; (void)ol;
    }
    // Direct simple path (compiler-friendly): 8 x uint32 hi + 8 x uint32 lo
    {
        size_t base = ((size_t)(pb + p) * CF + part * 32);
        uint32_t* hdst = (uint32_t*)(dHi + base);
        uint32_t* ldst = (uint32_t*)(dLo + base);
#pragma unroll
        for (int j = 0; j < 16; j++) {
            int c = part * 32 + j * 2;
            float v0 = sm[(c + 0) * 33 + p] * inv;
            float v1 = sm[(c + 1) * 33 + p] * inv;
            __nv_bfloat16 h0 = __float2bfloat16(v0), h1 = __float2bfloat16(v1);
            __nv_bfloat162 hp; hp.x = h0; hp.y = h1;
            __nv_bfloat16 l0 = __float2bfloat16(v0 - __bfloat162float(h0));
            __nv_bfloat16 l1 = __float2bfloat16(v1 - __bfloat162float(h1));
            __nv_bfloat162 lp; lp.x = l0; lp.y = l1;
            hdst[j] = *(uint32_t*)&hp;
            ldst[j] = *(uint32_t*)&lp;
        }
    }
}

// ---------------- 4) bilinear downsample 256->64 ----------------
__global__ void k_ufb(const float* __restrict__ ub) {
    int idx = blockIdx.x * 256 + threadIdx.x;
    if (idx >= HW * CO) return;
    int c = idx & 63, q = idx >> 6;
    int i = q >> 6, j = q & 63;
    const float sc = 255.0f / 63.0f;
    float ry = (float)i * sc, rx = (float)j * sc;
    int y0 = (int)ry, x0 = (int)rx;
    int y1 = min(y0 + 1, 255), x1 = min(x0 + 1, 255);
    float wy = ry - (float)y0, wx = rx - (float)x0;
    const float* b = ub + c * 65536;
    float v00 = b[y0 * 256 + x0], v01 = b[y0 * 256 + x1];
    float v10 = b[y1 * 256 + x0], v11 = b[y1 * 256 + x1];
    float r0 = v00 * (1.f - wy) + v10 * wy;
    float r1 = v01 * (1.f - wy) + v11 * wy;
    g_ufb[q * CO + c] = r0 * (1.f - wx) + r1 * wx;
}

// ---------------- 5) U0[c], Bk[k][c], nbk ----------------
__global__ void k_ub() {
    int c = blockIdx.x;
    __shared__ float s_acc[4];
    __shared__ int   s_n[3];
    if (threadIdx.x < 4) s_acc[threadIdx.x] = 0.f;
    if (threadIdx.x < 3) s_n[threadIdx.x] = 0;
    __syncthreads();
    float a0 = 0, b0 = 0, b1 = 0, b2 = 0;
    int n0 = 0, n1 = 0, n2 = 0;
    for (int q = threadIdx.x; q < HW; q += 256) {
        float u = g_ufb[q * CO + c];
        int code = g_codeB[q];
        a0 += u;
        if (code & 1) { b0 += u; n0++; }
        if (code & 2) { b1 += u; n1++; }
        if (code & 4) { b2 += u; n2++; }
    }
    atomicAdd(&s_acc[0], a0);
    atomicAdd(&s_acc[1], b0);
    atomicAdd(&s_acc[2], b1);
    atomicAdd(&s_acc[3], b2);
    if (c == 0) {
        atomicAdd(&s_n[0], n0); atomicAdd(&s_n[1], n1); atomicAdd(&s_n[2], n2);
    }
    __syncthreads();
    if (threadIdx.x == 0) g_U0[c] = s_acc[0];
    if (threadIdx.x < 3) {
        g_Bk[threadIdx.x * CO + c] = s_acc[1 + threadIdx.x];
        if (c == 0) g_nbk[threadIdx.x] = (float)s_n[threadIdx.x];
    }
}

// ---------------- 5b) build V^T planes ----------------
__global__ void k_V() {
    int idx = blockIdx.x * 256 + threadIdx.x;   // col*HW + q
    if (idx >= NV * HW) return;
    int col = idx >> 12, q = idx & 4095;
    float v = 0.f;
    int code = g_codeB[q];
    if (col < 192) {
        int k = col >> 6, c = col & 63;
        v = ((code >> k) & 1) ? g_ufb[q * CO + c] : 0.f;
    } else if (col < 195) {
        v = (float)((code >> (col - 192)) & 1);
    }
    __nv_bfloat16 h = __float2bfloat16(v);
    g_Vthi[idx] = h;
    g_Vtlo[idx] = __float2bfloat16(v - __bfloat162float(h));
}

// ---------------- 6) GEMM1: split-bf16, 128x128 tile, 4-stage k16 pipeline ----------------
#define G1_RS 48                       // smem row stride (bytes)
#define G1_PLANE (128 * G1_RS)         // 6144
#define G1_STAGE (4 * G1_PLANE)        // 24576: Ahi, Alo, Bhi, Blo
#define G1_SMEM  (4 * G1_STAGE)        // 98304

__device__ __forceinline__ void g1_prefetch(uint32_t sb, int s, int kc,
                                            int pb, int qb, int t) {
    int kof = kc * 16;
#pragma unroll
    for (int i = 0; i < 4; i++) {
        int v = t + i * 256;                     // 0..1023
        int plane = v >> 8, r = (v >> 1) & 127, seg = v & 1;
        uint32_t sa = sb + (uint32_t)(s * G1_STAGE + plane * G1_PLANE + r * G1_RS + seg * 16);
        const __nv_bfloat16* src = (plane == 0) ? g_faHi : (plane == 1) ? g_faLo
                                 : (plane == 2) ? g_fbHi : g_fbLo;
        int rowb = (plane < 2) ? pb : qb;
        cp16(sa, (const char*)src + ((size_t)(rowb + r) * CF + kof + seg * 8) * 2);
    }
}

__global__ void __launch_bounds__(256, 2) k_gemm_mma() {
    extern __shared__ char smem[];
    uint32_t sb = smem_u32(smem);
    int t = threadIdx.x, w = t >> 5, l = t & 31;
    int qb = blockIdx.x << 7, pb = blockIdx.y << 7;
    int wm = w >> 1, wn = w & 1;

    float acc[2][8][4] = {};

    int rowA = wm * 32 + (l & 15);
    int rowB = wn * 64 + (l & 15);
    uint32_t colb = (uint32_t)((l >> 4) << 4);

    g1_prefetch(sb, 0, 0, pb, qb, t); CP_COMMIT;
    g1_prefetch(sb, 1, 1, pb, qb, t); CP_COMMIT;
    g1_prefetch(sb, 2, 2, pb, qb, t); CP_COMMIT;

    for (int kc = 0; kc < 16; kc++) {
        CP_WAIT2;
        __syncthreads();
        if (kc <= 12) g1_prefetch(sb, (kc + 3) & 3, kc + 3, pb, qb, t);
        CP_COMMIT;

        uint32_t baseA = sb + (uint32_t)((kc & 3) * G1_STAGE);
        uint32_t baseB = baseA + 2 * G1_PLANE;

        uint32_t ah[2][4], al[2][4];
#pragma unroll
        for (int mi = 0; mi < 2; mi++) {
            uint32_t ad = baseA + (uint32_t)((rowA + mi * 16) * G1_RS) + colb;
            LDSM_X4(ah[mi][0], ah[mi][1], ah[mi][2], ah[mi][3], ad);
            LDSM_X4(al[mi][0], al[mi][1], al[mi][2], al[mi][3], ad + G1_PLANE);
        }
#pragma unroll
        for (int np = 0; np < 4; np++) {
            uint32_t bd = baseB + (uint32_t)((rowB + np * 16) * G1_RS) + colb;
            uint32_t bh[4], bl[4];
            LDSM_X4(bh[0], bh[1], bh[2], bh[3], bd);
            LDSM_X4(bl[0], bl[1], bl[2], bl[3], bd + G1_PLANE);
            mma_bf16(acc[0][np * 2 + 0], ah[0], bh[0], bh[2]);
            mma_bf16(acc[0][np * 2 + 1], ah[0], bh[1], bh[3]);
            mma_bf16(acc[1][np * 2 + 0], ah[1], bh[0], bh[2]);
            mma_bf16(acc[1][np * 2 + 1], ah[1], bh[1], bh[3]);
            mma_bf16(acc[0][np * 2 + 0], ah[0], bl[0], bl[2]);
            mma_bf16(acc[0][np * 2 + 1], ah[0], bl[1], bl[3]);
            mma_bf16(acc[1][np * 2 + 0], ah[1], bl[0], bl[2]);
            mma_bf16(acc[1][np * 2 + 1], ah[1], bl[1], bl[3]);
            mma_bf16(acc[0][np * 2 + 0], al[0], bh[0], bh[2]);
            mma_bf16(acc[0][np * 2 + 1], al[0], bh[1], bh[3]);
            mma_bf16(acc[1][np * 2 + 0], al[1], bh[0], bh[2]);
            mma_bf16(acc[1][np * 2 + 1], al[1], bh[1], bh[3]);
        }
    }

    // ---- epilogue: exp + bf16 hi/lo plane stores ----
    int prl = wm * 32 + (l >> 2);
    int qcl = wn * 64 + (l & 3) * 2;
#pragma unroll
    for (int mi = 0; mi < 2; mi++) {
#pragma unroll
        for (int nj = 0; nj < 8; nj++) {
#pragma unroll
            for (int half = 0; half < 2; half++) {
                int rloc = prl + mi * 16 + half * 8;
                int qloc = qcl + nj * 8;
                float x0 = __expf(fminf(ALPHA * acc[mi][nj][half * 2 + 0], 80.f));
                float x1 = __expf(fminf(ALPHA * acc[mi][nj][half * 2 + 1], 80.f));
                __nv_bfloat16 h0 = __float2bfloat16(x0);
                __nv_bfloat16 h1 = __float2bfloat16(x1);
                __nv_bfloat16 lo0 = __float2bfloat16(x0 - __bfloat162float(h0));
                __nv_bfloat16 lo1 = __float2bfloat16(x1 - __bfloat162float(h1));
                __nv_bfloat162 hp; hp.x = h0; hp.y = h1;
                __nv_bfloat162 lp; lp.x = lo0; lp.y = lo1;
                size_t idx = ((size_t)(pb + rloc) * HW + qb + qloc) >> 1;
                g_Xhi[idx] = *(uint32_t*)&hp;
                g_Xlo[idx] = *(uint32_t*)&lp;
            }
        }
    }
}

// ---------------- 7) GEMM2: W = X @ V^T, 4-stage k16 pipeline ----------------
#define G2_RS 48
#define G2_APLANE (64 * G2_RS)                    // 3072
#define G2_BPLANE (NV * G2_RS)                    // 9984
#define G2_STAGE (2 * G2_APLANE + 2 * G2_BPLANE)  // 26112
#define G2_SMEM  (4 * G2_STAGE)                   // 104448
#define G2_SLOTS (256 + 2 * NV * 2)               // 1088

__device__ __forceinline__ void g2_prefetch(uint32_t sb, int s, int qof, int pb, int t) {
#pragma unroll
    for (int i = 0; i < 5; i++) {
        int v = t + i * 256;
        if (v >= G2_SLOTS) break;
        if (v < 256) {
            int plane = v >> 7, r = (v >> 1) & 63, seg = v & 1;
            uint32_t sa = sb + (uint32_t)(s * G2_STAGE + plane * G2_APLANE + r * G2_RS + seg * 16);
            const uint32_t* xp = plane ? g_Xlo : g_Xhi;
            cp16(sa, (const char*)xp + ((size_t)(pb + r) * HW + qof) * 2 + seg * 16);
        } else {
            int v2 = v - 256;
            int plane = (v2 >= NV * 2) ? 1 : 0;
            int r = (v2 - plane * NV * 2) >> 1, seg = v2 & 1;
            uint32_t sa = sb + (uint32_t)(s * G2_STAGE + 2 * G2_APLANE + plane * G2_BPLANE + r * G2_RS + seg * 16);
            const __nv_bfloat16* vp = plane ? g_Vtlo : g_Vthi;
            cp16(sa, (const char*)vp + ((size_t)r * HW + qof + seg * 8) * 2);
        }
    }
}

__global__ void __launch_bounds__(256, 2) k_gemm2() {
    extern __shared__ char smem[];
    uint32_t sb = smem_u32(smem);
    int t = threadIdx.x, w = t >> 5, l = t & 31;
    int pb = blockIdx.x << 6;
    int q0 = blockIdx.y << 10;
    int wm = w & 3, wn = w >> 2;     // SMSP-balanced; wn0: 7 tiles, wn1: 6 tiles
    int nt = wn ? 6 : 7;

    float acc[14][4] = {};

    uint32_t arow = (uint32_t)((wm * 16 + (l & 15)) * G2_RS);
    uint32_t colb = (uint32_t)((l >> 4) << 4);

    g2_prefetch(sb, 0, q0, pb, t); CP_COMMIT;
    g2_prefetch(sb, 1, q0 + 16, pb, t); CP_COMMIT;
    g2_prefetch(sb, 2, q0 + 32, pb, t); CP_COMMIT;

    for (int kc = 0; kc < 64; kc++) {
        CP_WAIT2;
        __syncthreads();
        if (kc <= 60) g2_prefetch(sb, (kc + 3) & 3, q0 + (kc + 3) * 16, pb, t);
        CP_COMMIT;

        uint32_t baseA = sb + (uint32_t)((kc & 3) * G2_STAGE);
        uint32_t baseB = baseA + 2 * G2_APLANE;

        uint32_t ah[4], al[4];
        uint32_t ad = baseA + arow + colb;
        LDSM_X4(ah[0], ah[1], ah[2], ah[3], ad);
        LDSM_X4(al[0], al[1], al[2], al[3], ad + G2_APLANE);
#pragma unroll
        for (int np = 0; np < 7; np++) {
            if (np < nt) {
                uint32_t bd = baseB + (uint32_t)((wn * 112 + np * 16 + (l & 15)) * G2_RS) + colb;
                uint32_t bh[4], bl[4];
                LDSM_X4(bh[0], bh[1], bh[2], bh[3], bd);
                LDSM_X4(bl[0], bl[1], bl[2], bl[3], bd + G2_BPLANE);
                mma_bf16(acc[np * 2 + 0], ah, bh[0], bh[2]);
                mma_bf16(acc[np * 2 + 1], ah, bh[1], bh[3]);
                mma_bf16(acc[np * 2 + 0], ah, bl[0], bl[2]);
                mma_bf16(acc[np * 2 + 1], ah, bl[1], bl[3]);
                mma_bf16(acc[np * 2 + 0], al, bh[0], bh[2]);
                mma_bf16(acc[np * 2 + 1], al, bh[1], bh[3]);
            }
        }
    }

    // epilogue: fp32 partials
    int r0 = pb + wm * 16 + (l >> 2);
    int cb2 = (l & 3) * 2;
    float* Wp = g_Wpart + (size_t)blockIdx.y * HW * NV;
#pragma unroll
    for (int np = 0; np < 7; np++) {
        if (np < nt) {
#pragma unroll
            for (int n8 = 0; n8 < 2; n8++) {
                int col = wn * 112 + np * 16 + n8 * 8 + cb2;
                float* a = acc[np * 2 + n8];
                *(float2*)&Wp[(size_t)r0 * NV + col]       = make_float2(a[0], a[1]);
                *(float2*)&Wp[(size_t)(r0 + 8) * NV + col] = make_float2(a[2], a[3]);
            }
        }
    }
}

// ---------------- 8) combine (reads k-split partials directly) ----------------
__global__ void k_combine() {
    int idx = blockIdx.x * 256 + threadIdx.x;   // p*64 + c
    if (idx >= HW * CO) return;
    int p = idx >> 6, c = idx & 63;
    float comb = 0.f, msum = 0.f;
#pragma unroll
    for (int k = 0; k < 3; k++) {
        if (g_maskA[k * HW + p]) {
            msum += 1.f;
            float E = 0.f, Wv = 0.f;
#pragma unroll
            for (int ks = 0; ks < 4; ks++) {
                const float* Wp = g_Wpart + (size_t)ks * HW * NV + (size_t)p * NV;
                E  += Wp[192 + k];
                Wv += Wp[k * 64 + c];
            }
            float denom = E + (4096.0f - g_nbk[k]);
            comb += (Wv + g_U0[c] - g_Bk[k * CO + c]) / denom;
        }
    }
    g_aligned[idx] = comb / fmaxf(msum, 1.0f);
}

// ---------------- 9) bilinear upsample 64 -> 256 ----------------
__global__ void k_up(float* __restrict__ out) {
    int idx = blockIdx.x * 256 + threadIdx.x;
    if (idx >= CO * 65536) return;
    int c = idx >> 16, Y = (idx >> 8) & 255, X = idx & 255;
    const float sc = 63.0f / 255.0f;
    float ry = (float)Y * sc, rx = (float)X * sc;
    int y0 = (int)ry, x0 = (int)rx;
    int y1 = min(y0 + 1, 63), x1 = min(x0 + 1, 63);
    float wy = ry - (float)y0, wx = rx - (float)x0;
    const float* A = g_aligned;
    float v00 = A[((y0 << 6) + x0) * CO + c];
    float v01 = A[((y0 << 6) + x1) * CO + c];
    float v10 = A[((y1 << 6) + x0) * CO + c];
    float v11 = A[((y1 << 6) + x1) * CO + c];
    float r0 = v00 * (1.f - wy) + v10 * wy;
    float r1 = v01 * (1.f - wy) + v11 * wy;
    out[idx] = r0 * (1.f - wx) + r1 * wx;
}

// ---------------- launch ----------------
extern "C" void kernel_launch(void* const* d_in, const int* in_sizes, int n_in,
                              void* d_out, int out_size) {
    const float* ufb_in = (const float*)d_in[0];   // (1,64,256,256)
    const float* fa     = (const float*)d_in[1];   // (1,256,64,64)
    const int*   fap    = (const int*)  d_in[2];   // (1,4,256,256)
    const float* fb     = (const float*)d_in[3];   // (1,256,64,64)
    const int*   fbp    = (const int*)  d_in[4];   // (1,4,256,256)
    float* out = (float*)d_out;                    // (1,64,256,256)

    cudaFuncSetAttribute(k_gemm_mma, cudaFuncAttributeMaxDynamicSharedMemorySize, G1_SMEM);
    cudaFuncSetAttribute(k_gemm2,    cudaFuncAttributeMaxDynamicSharedMemorySize, G2_SMEM);

    k_masks<<<16, 256>>>(fap, fbp);
    k_mean<<<512, 256>>>(fa, fb);
    k_norm<<<dim3(128, 2), 256>>>(fa, fb);
    k_gemm_mma<<<dim3(32, 32), 256, G1_SMEM>>>();          // 4th launch -> profiled
    k_ufb<<<(HW * CO) / 256, 256>>>(ufb_in);
    k_ub<<<64, 256>>>();
    k_V<<<(NV * HW) / 256, 256>>>();
    k_gemm2<<<dim3(64, 4), 256, G2_SMEM>>>();
    k_combine<<<(HW * CO) / 256, 256>>>();
    k_up<<<(CO * 65536) / 256, 256>>>(out);
}